// round 13
// baseline (speedup 1.0000x reference)
#include <cuda_runtime.h>
#include <cuda_fp16.h>
#include <cstdint>

#define BATCH 8
#define SEQ   4096
#define DM    1024
#define CHUNK 128
#define NC    (SEQ / CHUNK)   // 32

// GEMM tiling: CTA 128x256, warp 64x32 (2M x 8N warps), 512 threads
#define TM 128
#define TN 256
#define KCG 64
#define NKC (DM / KCG)         // 16 k-chunks in global layout
#define KSTAGE 128             // K per pipeline stage (2 chunks)
#define NSTAGES (DM / KSTAGE)  // 8 stages
#define NTHREADS 512

#define A_CHUNK_BYTES 16384    // 128 rows x 128B
#define B_CHUNK_BYTES 32768    // 256 rows x 128B

// smem stage layout (per buffer): A 32K | B 64K   (2-deep pipeline)
#define A_OFF  0
#define B_OFF  32768
#define STAGE  98304
#define SMEM_DYN (2 * STAGE)   // 192 KB

// ------------- scratch: TILED + PRE-SWIZZLED layouts (bytes) ---------------
__device__ char g_Sf_t[(size_t)256 * NKC * A_CHUNK_BYTES];   // S fp16, 64 MB
__device__ char g_Wf_t[(size_t)4 * NKC * B_CHUNK_BYTES];     // W fp16, 2 MB
__device__ float g_partial[BATCH * NC * DM];
__device__ float g_carry[BATCH * NC * DM];

static __device__ __forceinline__ float sigmoidf_(float v) {
    return 1.0f / (1.0f + expf(-v));
}

static __device__ __forceinline__ uint32_t sw_off(uint32_t row, uint32_t col) {
    return (row << 7) + ((((col >> 3) ^ (row & 7)) << 4) + ((col & 7) << 1));
}

// ====================== baseline-PTX helpers ================================
__device__ __forceinline__ uint32_t smem_u32(const void* p) {
    uint32_t a;
    asm("{ .reg .u64 t; cvta.to.shared.u64 t, %1; cvt.u32.u64 %0, t; }" : "=r"(a) : "l"(p));
    return a;
}

#define MBARRIER_INIT(addr, count) \
    asm volatile("mbarrier.init.shared.b64 [%0], %1;" :: "r"((uint32_t)(addr)), "r"((uint32_t)(count)) : "memory")

#define MBARRIER_EXPECT_TX(addr, bytes) \
    asm volatile("mbarrier.arrive.expect_tx.shared.b64 _, [%0], %1;" \
        :: "r"((uint32_t)(addr)), "r"((uint32_t)(bytes)) : "memory")

#define MBARRIER_WAIT_PARITY(addr, parity) do { \
    uint32_t _mbar = (uint32_t)(addr); \
    uint32_t _par  = (uint32_t)(parity); \
    uint32_t _done; \
    asm volatile("{\n\t.reg .pred p;\n\t" \
        "mbarrier.try_wait.parity.acquire.cta.shared::cta.b64 p, [%1], %2;\n\t" \
        "selp.b32 %0, 1, 0, p;\n\t}" : "=r"(_done) : "r"(_mbar), "r"(_par) : "memory"); \
    if (!_done) { \
        asm volatile("{\n\t.reg .pred P1;\n\t" \
            "WL_%=:\n\t" \
            "mbarrier.try_wait.parity.acquire.cta.shared::cta.b64 P1, [%0], %1, 0x989680;\n\t" \
            "@P1 bra.uni WD_%=;\n\t" \
            "bra.uni WL_%=;\n\t" \
            "WD_%=:\n\t}" :: "r"(_mbar), "r"(_par) : "memory"); \
    } \
} while (0)

__device__ __forceinline__ void bulk_g2s(uint32_t dst, const void* src,
                                         uint32_t bytes, uint32_t mbar) {
    asm volatile(
        "cp.async.bulk.shared::cluster.global.mbarrier::complete_tx::bytes [%0], [%1], %2, [%3];"
        :: "r"(dst), "l"(src), "r"(bytes), "r"(mbar) : "memory");
}

__device__ __forceinline__ void ldsm_x4(uint32_t* r, uint32_t addr) {
    asm volatile("ldmatrix.sync.aligned.m8n8.x4.shared.b16 {%0,%1,%2,%3}, [%4];"
                 : "=r"(r[0]), "=r"(r[1]), "=r"(r[2]), "=r"(r[3]) : "r"(addr));
}

__device__ __forceinline__ void mma_f16(float* c, const uint32_t* a, const uint32_t* b) {
    asm volatile(
        "mma.sync.aligned.m16n8k16.row.col.f32.f16.f16.f32 "
        "{%0,%1,%2,%3}, {%4,%5,%6,%7}, {%8,%9}, {%0,%1,%2,%3};"
        : "+f"(c[0]), "+f"(c[1]), "+f"(c[2]), "+f"(c[3])
        : "r"(a[0]), "r"(a[1]), "r"(a[2]), "r"(a[3]), "r"(b[0]), "r"(b[1]));
}

// ====================== prep: EMA partial + W fp16 =========================
__global__ void prep_kernel(const float* __restrict__ x,
                            const float* __restrict__ dl,
                            const float* __restrict__ W) {
    const int tid = threadIdx.x;           // 1024
    if (blockIdx.x < BATCH * NC) {
        const int d  = tid;
        const int bc = blockIdx.x;
        const int b  = bc / NC;
        const int c  = bc % NC;
        const float a  = sigmoidf_(dl[d]);
        const float om = 1.0f - a;
        const float* xp = x + ((size_t)b * SEQ + (size_t)c * CHUNK) * DM + d;
        float s = 0.0f;
#pragma unroll 8
        for (int i = 0; i < CHUNK; i++) s = a * s + om * xp[(size_t)i * DM];
        g_partial[(size_t)bc * DM + d] = s;
    } else {
        const size_t i = ((size_t)(blockIdx.x - BATCH * NC)) * 1024 + tid;
        const uint32_t e = (uint32_t)(i >> 10);
        const uint32_t d = (uint32_t)(i & 1023);
        const uint32_t nt = e >> 8;
        const uint32_t r  = e & 255;
        const uint32_t kc = d >> 6;
        const uint32_t cc = d & 63;
        const size_t off = ((size_t)(nt * NKC + kc)) * B_CHUNK_BYTES + sw_off(r, cc);
        *(__half*)(g_Wf_t + off) = __float2half_rn(W[i]);
    }
}

__global__ void ema_carry_kernel(const float* __restrict__ dl) {
    const int d = threadIdx.x;
    const int b = blockIdx.x;
    const float a = sigmoidf_(dl[d]);
    float pw = a;
#pragma unroll
    for (int i = 0; i < 7; i++) pw *= pw;   // a^128
    float cur = 0.0f;
    for (int c = 0; c < NC; c++) {
        const size_t idx = ((size_t)b * NC + c) * DM + d;
        g_carry[idx] = cur;
        cur = pw * cur + g_partial[idx];
    }
}

__global__ void ema_final_kernel(const float* __restrict__ x,
                                 const float* __restrict__ dl) {
    const int d  = threadIdx.x;
    const int bc = blockIdx.x;
    const int b  = bc / NC;
    const int c  = bc % NC;
    const float a  = sigmoidf_(dl[d]);
    const float om = 1.0f - a;
    float s = g_carry[(size_t)bc * DM + d];
    const float* xp = x + ((size_t)b * SEQ + (size_t)c * CHUNK) * DM + d;

    const uint32_t mt = (uint32_t)((b * SEQ + c * CHUNK) >> 7);
    const uint32_t kc = (uint32_t)d >> 6;
    const uint32_t cc = (uint32_t)d & 63;
    const size_t tbase = ((size_t)(mt * NKC + kc)) * A_CHUNK_BYTES;

#pragma unroll 8
    for (int i = 0; i < CHUNK; i++) {
        s = a * s + om * xp[(size_t)i * DM];
        *(__half*)(g_Sf_t + tbase + sw_off((uint32_t)i, cc)) = __float2half_rn(s);
    }
}

// ====================== HMMA GEMM: phase-staggered mainloop =================
__global__ __launch_bounds__(NTHREADS, 1)
void gemm_mma_kernel(const float* __restrict__ x,
                     const float* __restrict__ bias,
                     const float* __restrict__ conv_w,
                     const float* __restrict__ conv_b,
                     float* __restrict__ out) {
    extern __shared__ __align__(128) char dsm[];
    __shared__ __align__(8) unsigned long long s_full[2];
    __shared__ float s_bias2[TN];
    __shared__ float s_cw[TN * 5];

    const int tid  = threadIdx.x;
    const int wid  = tid >> 5;
    const int lane = tid & 31;

    const int nt = blockIdx.x;               // 0..3
    const int mt = blockIdx.y;               // 0..255
    const int n0 = nt * TN;
    const int m0 = mt * TM;
    const int b_ = m0 >> 12;
    const int t0 = m0 & (SEQ - 1);

    const int wm = (wid & 1) * 64;            // 2 warps in M
    const int wn = (wid >> 1) * 32;           // 8 warps in N

    const uint32_t sbase = smem_u32(dsm);
    const uint32_t fb0 = smem_u32(&s_full[0]);
    const uint32_t fb1 = smem_u32(&s_full[1]);

    if (tid == 0) {
        MBARRIER_INIT(fb0, 1);
        MBARRIER_INIT(fb1, 1);
    }
    for (int i = tid; i < TN; i += NTHREADS) {
        const int e = n0 + i;
        s_bias2[i] = bias[e] + conv_b[e];
#pragma unroll
        for (int k = 0; k < 5; k++) s_cw[i * 5 + k] = conv_w[e * 5 + k];
    }
    __syncthreads();

    const char* Abase = g_Sf_t + (size_t)(mt * NKC) * A_CHUNK_BYTES;
    const char* Bbase = g_Wf_t + (size_t)(nt * NKC) * B_CHUNK_BYTES;

    // prologue: stage 0 -> buf 0
    if (tid == 0) {
        MBARRIER_EXPECT_TX(fb0, STAGE);
        bulk_g2s(sbase + A_OFF, Abase, 2 * A_CHUNK_BYTES, fb0);
        bulk_g2s(sbase + B_OFF, Bbase, 2 * B_CHUNK_BYTES, fb0);
    }

    float acc[4][4][4];
#pragma unroll
    for (int a1 = 0; a1 < 4; a1++)
#pragma unroll
        for (int a2 = 0; a2 < 4; a2++)
#pragma unroll
            for (int a3 = 0; a3 < 4; a3++) acc[a1][a2][a3] = 0.0f;

    const int lr = lane & 15;
    const int lh = lane >> 4;
    const uint32_t xorv = (uint32_t)((lr & 7) << 4);
    uint32_t arow[4], brow[2];
#pragma unroll
    for (int i = 0; i < 4; i++) arow[i] = (uint32_t)(wm + i * 16 + lr) << 7;
#pragma unroll
    for (int i = 0; i < 2; i++) brow[i] = (uint32_t)(wn + i * 16 + lr) << 7;

    // per-warp phase offset: desynchronize warps across the 8 k16 slices
    const uint32_t wphase = (uint32_t)(wid & 7);

    int ph0 = 0, ph1 = 0;

#pragma unroll 1
    for (int kc = 0; kc < NSTAGES; kc++) {
        const int cur = kc & 1;

        if (kc + 1 < NSTAGES && tid == 0) {
            const uint32_t nb   = sbase + (uint32_t)(cur ^ 1) * STAGE;
            const uint32_t nbar = (cur ^ 1) ? fb1 : fb0;
            MBARRIER_EXPECT_TX(nbar, STAGE);
            bulk_g2s(nb + A_OFF, Abase + (size_t)(kc + 1) * 2 * A_CHUNK_BYTES, 2 * A_CHUNK_BYTES, nbar);
            bulk_g2s(nb + B_OFF, Bbase + (size_t)(kc + 1) * 2 * B_CHUNK_BYTES, 2 * B_CHUNK_BYTES, nbar);
        }

        if (cur == 0) { MBARRIER_WAIT_PARITY(fb0, ph0); ph0 ^= 1; }
        else          { MBARRIER_WAIT_PARITY(fb1, ph1); ph1 ^= 1; }

        const uint32_t sb = sbase + (uint32_t)cur * STAGE;

#pragma unroll
        for (int ks = 0; ks < 8; ks++) {
            // staggered slice index: warps start at different phases
            const uint32_t ke = ((uint32_t)ks + wphase) & 7;
            const uint32_t aof = sb + A_OFF + ((ke >> 2) * A_CHUNK_BYTES);
            const uint32_t bof = sb + B_OFF + ((ke >> 2) * B_CHUNK_BYTES);
            const uint32_t chunk = (((ke & 3) << 5) + ((uint32_t)lh << 4)) ^ xorv;

            uint32_t af[4][4];
#pragma unroll
            for (int m2 = 0; m2 < 4; m2++)
                ldsm_x4(af[m2], aof + arow[m2] + chunk);

#pragma unroll
            for (int p = 0; p < 2; p++) {
                uint32_t r0[4];
                uint32_t bh0[2], bh1[2];
                ldsm_x4(r0, bof + brow[p] + chunk);
                bh0[0] = r0[0]; bh0[1] = r0[2];
                bh1[0] = r0[1]; bh1[1] = r0[3];
#pragma unroll
                for (int m2 = 0; m2 < 4; m2++) {
                    mma_f16(acc[m2][2 * p],     af[m2], bh0);
                    mma_f16(acc[m2][2 * p + 1], af[m2], bh1);
                }
            }
        }
        __syncthreads();
    }

    // --- epilogue: + bias + conv_b + depthwise conv(x, K=5), write out -----
    const int lq = lane >> 2;
    const int lc = (lane & 3) * 2;
    const float* xb = x + (size_t)b_ * SEQ * DM;

#pragma unroll
    for (int m2 = 0; m2 < 4; m2++) {
#pragma unroll
        for (int half = 0; half < 2; half++) {
            const int t = t0 + wm + m2 * 16 + lq + half * 8;
            float2 v[4];
#pragma unroll
            for (int n2 = 0; n2 < 4; n2++) {
                const int ei = wn + n2 * 8 + lc;
                v[n2].x = acc[m2][n2][half * 2 + 0] + s_bias2[ei];
                v[n2].y = acc[m2][n2][half * 2 + 1] + s_bias2[ei + 1];
            }
#pragma unroll
            for (int k = 0; k < 5; k++) {
                const int tt = t - 2 + k;
                if (tt >= 0 && tt < SEQ) {
                    const float* xr = xb + (size_t)tt * DM + n0;
#pragma unroll
                    for (int n2 = 0; n2 < 4; n2++) {
                        const int ei = wn + n2 * 8 + lc;
                        const float2 xv = *(const float2*)(xr + ei);
                        v[n2].x += s_cw[ei * 5 + k] * xv.x;
                        v[n2].y += s_cw[(ei + 1) * 5 + k] * xv.y;
                    }
                }
            }
            float* op = out + ((size_t)b_ * SEQ + (size_t)t) * DM + n0;
#pragma unroll
            for (int n2 = 0; n2 < 4; n2++)
                *(float2*)(op + wn + n2 * 8 + lc) = v[n2];
        }
    }
}

// ---------------------------------------------------------------------------
extern "C" void kernel_launch(void* const* d_in, const int* in_sizes, int n_in,
                              void* d_out, int out_size) {
    const float* x      = (const float*)d_in[0];
    const float* dl     = (const float*)d_in[1];
    const float* W      = (const float*)d_in[2];
    const float* bias   = (const float*)d_in[3];
    const float* conv_w = (const float*)d_in[4];
    const float* conv_b = (const float*)d_in[5];
    float* out = (float*)d_out;

    cudaFuncSetAttribute(gemm_mma_kernel,
                         cudaFuncAttributeMaxDynamicSharedMemorySize, SMEM_DYN);

    prep_kernel<<<BATCH * NC + (DM * DM) / 1024, 1024>>>(x, dl, W);
    ema_carry_kernel<<<BATCH, DM>>>(dl);
    ema_final_kernel<<<BATCH * NC, DM>>>(x, dl);

    dim3 grid(DM / TN, (BATCH * SEQ) / TM);   // (4, 256)
    gemm_mma_kernel<<<grid, NTHREADS, SMEM_DYN>>>(x, bias, conv_w, conv_b, out);
}

// round 14
// speedup vs baseline: 1.1660x; 1.1660x over previous
#include <cuda_runtime.h>
#include <cuda_fp16.h>
#include <cstdint>

#define BATCH 8
#define SEQ   4096
#define DM    1024
#define CHUNK 128
#define NC    (SEQ / CHUNK)   // 32

// GEMM tiling: CTA 128x128, warp 64x32 (2M x 4N warps), 256 threads, 2 CTAs/SM
#define TM 128
#define TN 128
#define KCG 64
#define NKC (DM / KCG)         // 16 k-chunks
#define NTHREADS 256

#define A_CHUNK_BYTES 16384    // 128 rows x 128B
#define B_CHUNK_BYTES 16384    // 128 rows x 128B

// smem stage layout (per buffer): A 16K | B 16K   (2-deep pipeline)
#define A_OFF  0
#define B_OFF  16384
#define STAGE  32768
#define SMEM_DYN (2 * STAGE)   // 64 KB per CTA -> 2 CTAs/SM

// ------------- scratch: TILED + PRE-SWIZZLED layouts (bytes) ---------------
__device__ char g_Sf_t[(size_t)256 * NKC * A_CHUNK_BYTES];   // S fp16, 64 MB
__device__ char g_Wf_t[(size_t)8 * NKC * B_CHUNK_BYTES];     // W fp16, 2 MB
__device__ float g_partial[BATCH * NC * DM];
__device__ float g_carry[BATCH * NC * DM];

static __device__ __forceinline__ float sigmoidf_(float v) {
    return 1.0f / (1.0f + expf(-v));
}

static __device__ __forceinline__ uint32_t sw_off(uint32_t row, uint32_t col) {
    return (row << 7) + ((((col >> 3) ^ (row & 7)) << 4) + ((col & 7) << 1));
}

// ====================== baseline-PTX helpers ================================
__device__ __forceinline__ uint32_t smem_u32(const void* p) {
    uint32_t a;
    asm("{ .reg .u64 t; cvta.to.shared.u64 t, %1; cvt.u32.u64 %0, t; }" : "=r"(a) : "l"(p));
    return a;
}

#define MBARRIER_INIT(addr, count) \
    asm volatile("mbarrier.init.shared.b64 [%0], %1;" :: "r"((uint32_t)(addr)), "r"((uint32_t)(count)) : "memory")

#define MBARRIER_EXPECT_TX(addr, bytes) \
    asm volatile("mbarrier.arrive.expect_tx.shared.b64 _, [%0], %1;" \
        :: "r"((uint32_t)(addr)), "r"((uint32_t)(bytes)) : "memory")

#define MBARRIER_WAIT_PARITY(addr, parity) do { \
    uint32_t _mbar = (uint32_t)(addr); \
    uint32_t _par  = (uint32_t)(parity); \
    uint32_t _done; \
    asm volatile("{\n\t.reg .pred p;\n\t" \
        "mbarrier.try_wait.parity.acquire.cta.shared::cta.b64 p, [%1], %2;\n\t" \
        "selp.b32 %0, 1, 0, p;\n\t}" : "=r"(_done) : "r"(_mbar), "r"(_par) : "memory"); \
    if (!_done) { \
        asm volatile("{\n\t.reg .pred P1;\n\t" \
            "WL_%=:\n\t" \
            "mbarrier.try_wait.parity.acquire.cta.shared::cta.b64 P1, [%0], %1, 0x989680;\n\t" \
            "@P1 bra.uni WD_%=;\n\t" \
            "bra.uni WL_%=;\n\t" \
            "WD_%=:\n\t}" :: "r"(_mbar), "r"(_par) : "memory"); \
    } \
} while (0)

__device__ __forceinline__ void bulk_g2s(uint32_t dst, const void* src,
                                         uint32_t bytes, uint32_t mbar) {
    asm volatile(
        "cp.async.bulk.shared::cluster.global.mbarrier::complete_tx::bytes [%0], [%1], %2, [%3];"
        :: "r"(dst), "l"(src), "r"(bytes), "r"(mbar) : "memory");
}

__device__ __forceinline__ void ldsm_x4(uint32_t* r, uint32_t addr) {
    asm volatile("ldmatrix.sync.aligned.m8n8.x4.shared.b16 {%0,%1,%2,%3}, [%4];"
                 : "=r"(r[0]), "=r"(r[1]), "=r"(r[2]), "=r"(r[3]) : "r"(addr));
}

__device__ __forceinline__ void mma_f16(float* c, const uint32_t* a, const uint32_t* b) {
    asm volatile(
        "mma.sync.aligned.m16n8k16.row.col.f32.f16.f16.f32 "
        "{%0,%1,%2,%3}, {%4,%5,%6,%7}, {%8,%9}, {%0,%1,%2,%3};"
        : "+f"(c[0]), "+f"(c[1]), "+f"(c[2]), "+f"(c[3])
        : "r"(a[0]), "r"(a[1]), "r"(a[2]), "r"(a[3]), "r"(b[0]), "r"(b[1]));
}

// ====================== prep: EMA partial + W fp16 =========================
__global__ void prep_kernel(const float* __restrict__ x,
                            const float* __restrict__ dl,
                            const float* __restrict__ W) {
    const int tid = threadIdx.x;           // 1024
    if (blockIdx.x < BATCH * NC) {
        const int d  = tid;
        const int bc = blockIdx.x;
        const int b  = bc / NC;
        const int c  = bc % NC;
        const float a  = sigmoidf_(dl[d]);
        const float om = 1.0f - a;
        const float* xp = x + ((size_t)b * SEQ + (size_t)c * CHUNK) * DM + d;
        float s = 0.0f;
#pragma unroll 8
        for (int i = 0; i < CHUNK; i++) s = a * s + om * xp[(size_t)i * DM];
        g_partial[(size_t)bc * DM + d] = s;
    } else {
        const size_t i = ((size_t)(blockIdx.x - BATCH * NC)) * 1024 + tid;
        const uint32_t e = (uint32_t)(i >> 10);
        const uint32_t d = (uint32_t)(i & 1023);
        const uint32_t nt = e >> 7;            // 128-row n-tile (0..7)
        const uint32_t r  = e & 127;
        const uint32_t kc = d >> 6;
        const uint32_t cc = d & 63;
        const size_t off = ((size_t)(nt * NKC + kc)) * B_CHUNK_BYTES + sw_off(r, cc);
        *(__half*)(g_Wf_t + off) = __float2half_rn(W[i]);
    }
}

__global__ void ema_carry_kernel(const float* __restrict__ dl) {
    const int d = threadIdx.x;
    const int b = blockIdx.x;
    const float a = sigmoidf_(dl[d]);
    float pw = a;
#pragma unroll
    for (int i = 0; i < 7; i++) pw *= pw;   // a^128
    float cur = 0.0f;
    for (int c = 0; c < NC; c++) {
        const size_t idx = ((size_t)b * NC + c) * DM + d;
        g_carry[idx] = cur;
        cur = pw * cur + g_partial[idx];
    }
}

__global__ void ema_final_kernel(const float* __restrict__ x,
                                 const float* __restrict__ dl) {
    const int d  = threadIdx.x;
    const int bc = blockIdx.x;
    const int b  = bc / NC;
    const int c  = bc % NC;
    const float a  = sigmoidf_(dl[d]);
    const float om = 1.0f - a;
    float s = g_carry[(size_t)bc * DM + d];
    const float* xp = x + ((size_t)b * SEQ + (size_t)c * CHUNK) * DM + d;

    const uint32_t mt = (uint32_t)((b * SEQ + c * CHUNK) >> 7);
    const uint32_t kc = (uint32_t)d >> 6;
    const uint32_t cc = (uint32_t)d & 63;
    const size_t tbase = ((size_t)(mt * NKC + kc)) * A_CHUNK_BYTES;

#pragma unroll 8
    for (int i = 0; i < CHUNK; i++) {
        s = a * s + om * xp[(size_t)i * DM];
        *(__half*)(g_Sf_t + tbase + sw_off((uint32_t)i, cc)) = __float2half_rn(s);
    }
}

// ====================== HMMA GEMM: 2 CTAs/SM ================================
__global__ __launch_bounds__(NTHREADS, 2)
void gemm_mma_kernel(const float* __restrict__ x,
                     const float* __restrict__ bias,
                     const float* __restrict__ conv_w,
                     const float* __restrict__ conv_b,
                     float* __restrict__ out) {
    extern __shared__ __align__(128) char dsm[];
    __shared__ __align__(8) unsigned long long s_full[2];
    __shared__ float s_bias2[TN];
    __shared__ float s_cw[TN * 5];

    const int tid  = threadIdx.x;
    const int wid  = tid >> 5;
    const int lane = tid & 31;

    const int nt = blockIdx.x;               // 0..7
    const int mt = blockIdx.y;               // 0..255
    const int n0 = nt * TN;
    const int m0 = mt * TM;
    const int b_ = m0 >> 12;
    const int t0 = m0 & (SEQ - 1);

    const int wm = (wid & 1) * 64;            // 2 warps in M
    const int wn = (wid >> 1) * 32;           // 4 warps in N

    const uint32_t sbase = smem_u32(dsm);
    const uint32_t fb0 = smem_u32(&s_full[0]);
    const uint32_t fb1 = smem_u32(&s_full[1]);

    if (tid == 0) {
        MBARRIER_INIT(fb0, 1);
        MBARRIER_INIT(fb1, 1);
    }
    for (int i = tid; i < TN; i += NTHREADS) {
        const int e = n0 + i;
        s_bias2[i] = bias[e] + conv_b[e];
#pragma unroll
        for (int k = 0; k < 5; k++) s_cw[i * 5 + k] = conv_w[e * 5 + k];
    }
    __syncthreads();

    const char* Abase = g_Sf_t + (size_t)(mt * NKC) * A_CHUNK_BYTES;
    const char* Bbase = g_Wf_t + (size_t)(nt * NKC) * B_CHUNK_BYTES;

    // prologue: stage 0 -> buf 0
    if (tid == 0) {
        MBARRIER_EXPECT_TX(fb0, STAGE);
        bulk_g2s(sbase + A_OFF, Abase, A_CHUNK_BYTES, fb0);
        bulk_g2s(sbase + B_OFF, Bbase, B_CHUNK_BYTES, fb0);
    }

    float acc[4][4][4];
#pragma unroll
    for (int a1 = 0; a1 < 4; a1++)
#pragma unroll
        for (int a2 = 0; a2 < 4; a2++)
#pragma unroll
            for (int a3 = 0; a3 < 4; a3++) acc[a1][a2][a3] = 0.0f;

    const int lr = lane & 15;
    const int lh = lane >> 4;
    const uint32_t xorv = (uint32_t)((lr & 7) << 4);
    uint32_t arow[4], brow[2];
#pragma unroll
    for (int i = 0; i < 4; i++) arow[i] = (uint32_t)(wm + i * 16 + lr) << 7;
#pragma unroll
    for (int i = 0; i < 2; i++) brow[i] = (uint32_t)(wn + i * 16 + lr) << 7;

    int ph0 = 0, ph1 = 0;

#pragma unroll 1
    for (int kc = 0; kc < NKC; kc++) {
        const int cur = kc & 1;

        if (kc + 1 < NKC && tid == 0) {
            const uint32_t nb   = sbase + (uint32_t)(cur ^ 1) * STAGE;
            const uint32_t nbar = (cur ^ 1) ? fb1 : fb0;
            MBARRIER_EXPECT_TX(nbar, STAGE);
            bulk_g2s(nb + A_OFF, Abase + (size_t)(kc + 1) * A_CHUNK_BYTES, A_CHUNK_BYTES, nbar);
            bulk_g2s(nb + B_OFF, Bbase + (size_t)(kc + 1) * B_CHUNK_BYTES, B_CHUNK_BYTES, nbar);
        }

        if (cur == 0) { MBARRIER_WAIT_PARITY(fb0, ph0); ph0 ^= 1; }
        else          { MBARRIER_WAIT_PARITY(fb1, ph1); ph1 ^= 1; }

        const uint32_t sb  = sbase + (uint32_t)cur * STAGE;
        const uint32_t aof = sb + A_OFF;
        const uint32_t bof = sb + B_OFF;

#pragma unroll
        for (int ks = 0; ks < 4; ks++) {
            const uint32_t chunk = ((uint32_t)((ks << 5) + (lh << 4))) ^ xorv;

            uint32_t af[4][4];
#pragma unroll
            for (int m2 = 0; m2 < 4; m2++)
                ldsm_x4(af[m2], aof + arow[m2] + chunk);

#pragma unroll
            for (int p = 0; p < 2; p++) {
                uint32_t r0[4];
                uint32_t bh0[2], bh1[2];
                ldsm_x4(r0, bof + brow[p] + chunk);
                bh0[0] = r0[0]; bh0[1] = r0[2];
                bh1[0] = r0[1]; bh1[1] = r0[3];
#pragma unroll
                for (int m2 = 0; m2 < 4; m2++) {
                    mma_f16(acc[m2][2 * p],     af[m2], bh0);
                    mma_f16(acc[m2][2 * p + 1], af[m2], bh1);
                }
            }
        }
        __syncthreads();
    }

    // --- epilogue: + bias + conv_b + depthwise conv(x, K=5), write out -----
    const int lq = lane >> 2;
    const int lc = (lane & 3) * 2;
    const float* xb = x + (size_t)b_ * SEQ * DM;

#pragma unroll
    for (int m2 = 0; m2 < 4; m2++) {
#pragma unroll
        for (int half = 0; half < 2; half++) {
            const int t = t0 + wm + m2 * 16 + lq + half * 8;
            float2 v[4];
#pragma unroll
            for (int n2 = 0; n2 < 4; n2++) {
                const int ei = wn + n2 * 8 + lc;
                v[n2].x = acc[m2][n2][half * 2 + 0] + s_bias2[ei];
                v[n2].y = acc[m2][n2][half * 2 + 1] + s_bias2[ei + 1];
            }
#pragma unroll
            for (int k = 0; k < 5; k++) {
                const int tt = t - 2 + k;
                if (tt >= 0 && tt < SEQ) {
                    const float* xr = xb + (size_t)tt * DM + n0;
#pragma unroll
                    for (int n2 = 0; n2 < 4; n2++) {
                        const int ei = wn + n2 * 8 + lc;
                        const float2 xv = *(const float2*)(xr + ei);
                        v[n2].x += s_cw[ei * 5 + k] * xv.x;
                        v[n2].y += s_cw[(ei + 1) * 5 + k] * xv.y;
                    }
                }
            }
            float* op = out + ((size_t)b_ * SEQ + (size_t)t) * DM + n0;
#pragma unroll
            for (int n2 = 0; n2 < 4; n2++)
                *(float2*)(op + wn + n2 * 8 + lc) = v[n2];
        }
    }
}

// ---------------------------------------------------------------------------
extern "C" void kernel_launch(void* const* d_in, const int* in_sizes, int n_in,
                              void* d_out, int out_size) {
    const float* x      = (const float*)d_in[0];
    const float* dl     = (const float*)d_in[1];
    const float* W      = (const float*)d_in[2];
    const float* bias   = (const float*)d_in[3];
    const float* conv_w = (const float*)d_in[4];
    const float* conv_b = (const float*)d_in[5];
    float* out = (float*)d_out;

    cudaFuncSetAttribute(gemm_mma_kernel,
                         cudaFuncAttributeMaxDynamicSharedMemorySize, SMEM_DYN);

    prep_kernel<<<BATCH * NC + (DM * DM) / 1024, 1024>>>(x, dl, W);
    ema_carry_kernel<<<BATCH, DM>>>(dl);
    ema_final_kernel<<<BATCH * NC, DM>>>(x, dl);

    dim3 grid(DM / TN, (BATCH * SEQ) / TM);   // (8, 256)
    gemm_mma_kernel<<<grid, NTHREADS, SMEM_DYN>>>(x, bias, conv_w, conv_b, out);
}